// round 1
// baseline (speedup 1.0000x reference)
#include <cuda_runtime.h>
#include <math.h>

#define NN    4096
#define NF    512
#define NH    64
#define NC    40
#define HEADS 4
#define NE    131072
#define ADJW  128          // 4096 bits / 32 per row
#define CAP   416          // neighbor list capacity per row (mean deg ~32)
#define ALPHA 0.2f

// ---------------- scratch (device globals; no allocation allowed) ----------
__device__ unsigned g_adj[NN * ADJW];            // 2 MB bitmask adjacency
__device__ int      g_is32;                      // edge_index dtype flag
__device__ float    g_Wh1[HEADS * NN * NH];      // 4 MB  [h][i][c]
__device__ float    g_src1[HEADS * NN];
__device__ float    g_dst1[HEADS * NN];
__device__ float    g_h[NN * HEADS * NH];        // 4 MB  [i][h*64+c]  (post-elu concat)
__device__ float    g_Wh2[NN * NC];
__device__ float    g_src2[NN];
__device__ float    g_dst2[NN];

// ---------------- warp reductions ----------------
__device__ __forceinline__ float warpMax(float v) {
#pragma unroll
    for (int o = 16; o; o >>= 1) v = fmaxf(v, __shfl_xor_sync(0xffffffffu, v, o));
    return v;
}
__device__ __forceinline__ float warpSum(float v) {
#pragma unroll
    for (int o = 16; o; o >>= 1) v += __shfl_xor_sync(0xffffffffu, v, o);
    return v;
}

// ---------------- init / adjacency build ----------------
__global__ void k_zero() {
    int i = blockIdx.x * blockDim.x + threadIdx.x;
    if (i < NN * ADJW) g_adj[i] = 0u;
    if (i == 0) g_is32 = 0;
}

// Detect whether edge_index is stored as int32 (jax x64 disabled) or int64.
// Read the first 1MB as int64 words: int32-packed pairs produce values >= 2^32
// almost surely; genuine int64 node ids are always in [0, NN).
__global__ void k_detect(const void* e) {
    const long long* p = (const long long*)e;
    int i = blockIdx.x * blockDim.x + threadIdx.x;
    bool bad = false;
    for (int k = i; k < NE; k += gridDim.x * blockDim.x) {
        long long v = p[k];
        if (v < 0 || v >= NN) bad = true;
    }
    if (bad) g_is32 = 1;
}

__global__ void k_scatter(const void* e) {
    int k = blockIdx.x * blockDim.x + threadIdx.x;
    if (k >= NE) return;
    int s, d;
    if (g_is32) {
        const int* p = (const int*)e;
        s = p[k]; d = p[k + NE];
    } else {
        const long long* p = (const long long*)e;
        s = (int)p[k]; d = (int)p[k + NE];
    }
    atomicOr(&g_adj[s * ADJW + (d >> 5)], 1u << (d & 31));
}

// ---------------- layer-1 GEMM: Wh1[h] = x @ W1[h] + b1[h] ----------------
// grid (64, 4) blocks of 256 threads; 64x64 output tile, 4x4 register blocking.
__global__ __launch_bounds__(256) void k_gemm1(const float* __restrict__ x,
                                               const float* __restrict__ W,
                                               const float* __restrict__ b) {
    __shared__ float As[16][68];   // As[k][m]
    __shared__ float Bs[16][68];   // Bs[k][n]
    int h  = blockIdx.y;
    int m0 = blockIdx.x * 64;
    const float* Wp = W + (size_t)h * NF * NH;
    int tid = threadIdx.x;
    int tx = tid & 15, ty = tid >> 4;

    float acc[4][4];
#pragma unroll
    for (int i = 0; i < 4; i++)
#pragma unroll
        for (int j = 0; j < 4; j++) acc[i][j] = 0.f;

    int lm  = tid >> 2;            // 0..63
    int lk  = (tid & 3) * 4;       // 0,4,8,12
    int lk2 = tid >> 4;            // 0..15
    int ln  = (tid & 15) * 4;      // 0..60

    for (int k0 = 0; k0 < NF; k0 += 16) {
        float4 va = *(const float4*)(x + (size_t)(m0 + lm) * NF + k0 + lk);
        As[lk + 0][lm] = va.x; As[lk + 1][lm] = va.y;
        As[lk + 2][lm] = va.z; As[lk + 3][lm] = va.w;
        float4 vb = *(const float4*)(Wp + (size_t)(k0 + lk2) * NH + ln);
        Bs[lk2][ln + 0] = vb.x; Bs[lk2][ln + 1] = vb.y;
        Bs[lk2][ln + 2] = vb.z; Bs[lk2][ln + 3] = vb.w;
        __syncthreads();
#pragma unroll
        for (int kk = 0; kk < 16; kk++) {
            float a0 = As[kk][ty * 4 + 0], a1 = As[kk][ty * 4 + 1];
            float a2 = As[kk][ty * 4 + 2], a3 = As[kk][ty * 4 + 3];
            float b0 = Bs[kk][tx * 4 + 0], b1 = Bs[kk][tx * 4 + 1];
            float b2 = Bs[kk][tx * 4 + 2], b3 = Bs[kk][tx * 4 + 3];
            acc[0][0] += a0 * b0; acc[0][1] += a0 * b1; acc[0][2] += a0 * b2; acc[0][3] += a0 * b3;
            acc[1][0] += a1 * b0; acc[1][1] += a1 * b1; acc[1][2] += a1 * b2; acc[1][3] += a1 * b3;
            acc[2][0] += a2 * b0; acc[2][1] += a2 * b1; acc[2][2] += a2 * b2; acc[2][3] += a2 * b3;
            acc[3][0] += a3 * b0; acc[3][1] += a3 * b1; acc[3][2] += a3 * b2; acc[3][3] += a3 * b3;
        }
        __syncthreads();
    }
#pragma unroll
    for (int ii = 0; ii < 4; ii++)
#pragma unroll
        for (int jj = 0; jj < 4; jj++)
            g_Wh1[((size_t)h * NN + m0 + ty * 4 + ii) * NH + tx * 4 + jj] =
                acc[ii][jj] + b[h * NH + tx * 4 + jj];
}

// ---------------- layer-1 src/dst vectors ----------------
// block 128 = 4 warps (one per head); grid NN (one row per block).
__global__ __launch_bounds__(128) void k_srcdst1(const float* __restrict__ a1) {
    int i = blockIdx.x;
    int h = threadIdx.x >> 5;
    int lane = threadIdx.x & 31;
    const float* whr = g_Wh1 + ((size_t)h * NN + i) * NH;
    float w0 = whr[lane], w1 = whr[lane + 32];
    const float* a = a1 + h * 2 * NH;
    float s = w0 * a[lane]      + w1 * a[lane + 32];
    float t = w0 * a[NH + lane] + w1 * a[NH + lane + 32];
    s = warpSum(s); t = warpSum(t);
    if (lane == 0) { g_src1[h * NN + i] = s; g_dst1[h * NN + i] = t; }
}

// ---------------- layer-1 sparse attention + elu + concat ----------------
// block 128 = 4 warps, one (row, head) per warp.
__global__ __launch_bounds__(128) void k_att1(const float* __restrict__ ab1) {
    __shared__ unsigned short s_nbr[4][CAP];
    __shared__ float          s_pe[4][CAP];
    int i = blockIdx.x;
    int h = threadIdx.x >> 5, lane = threadIdx.x & 31;

    const unsigned* row = g_adj + (size_t)i * ADJW;
    const float* dst = g_dst1 + (size_t)h * NN;
    float srci = g_src1[(size_t)h * NN + i] + ab1[h];

    // Phase A: deterministic neighbor gather (popc + warp exclusive scan).
    unsigned w[4]; int myc = 0;
#pragma unroll
    for (int q = 0; q < 4; q++) { w[q] = row[lane + 32 * q]; myc += __popc(w[q]); }
    int ofs = myc;
#pragma unroll
    for (int o = 1; o < 32; o <<= 1) {
        int v = __shfl_up_sync(0xffffffffu, ofs, o);
        if (lane >= o) ofs += v;
    }
    int cnt  = __shfl_sync(0xffffffffu, ofs, 31);
    int base = ofs - myc;
#pragma unroll
    for (int q = 0; q < 4; q++) {
        unsigned ww = w[q];
        while (ww) {
            int bpos = __ffs(ww) - 1; ww &= ww - 1;
            int j = (lane + 32 * q) * 32 + bpos;
            if (base < CAP) {
                float e = srci + dst[j];
                e = e > 0.f ? e : ALPHA * e;
                s_nbr[h][base] = (unsigned short)j;
                s_pe[h][base]  = e;
            }
            base++;
        }
    }
    __syncwarp();

    const float* Wh = g_Wh1 + (size_t)h * NN * NH;
    float acc0 = 0.f, acc1 = 0.f, sden;
    int c0 = lane, c1 = lane + 32;

    if (cnt > 0 && cnt <= CAP) {
        float m = -1e30f;
        for (int k = lane; k < cnt; k += 32) m = fmaxf(m, s_pe[h][k]);
        m = warpMax(m);
        float s = 0.f;
        for (int k = lane; k < cnt; k += 32) {
            float p = expf(s_pe[h][k] - m); s_pe[h][k] = p; s += p;
        }
        sden = warpSum(s);
        __syncwarp();
        for (int k = 0; k < cnt; k++) {
            float p = s_pe[h][k];
            const float* wr = Wh + (size_t)s_nbr[h][k] * NH;
            acc0 += p * wr[c0]; acc1 += p * wr[c1];
        }
    } else if (cnt == 0) {
        // all entries masked to NEG -> uniform softmax over all N columns
        for (int j = 0; j < NN; j++) {
            const float* wr = Wh + (size_t)j * NH;
            acc0 += wr[c0]; acc1 += wr[c1];
        }
        sden = (float)NN;
    } else {
        // overflow fallback: serial exact path
        float m = -1e30f;
        for (int j = 0; j < NN; j++)
            if ((row[j >> 5] >> (j & 31)) & 1u) {
                float e = srci + dst[j]; e = e > 0.f ? e : ALPHA * e;
                m = fmaxf(m, e);
            }
        sden = 0.f;
        for (int j = 0; j < NN; j++)
            if ((row[j >> 5] >> (j & 31)) & 1u) {
                float e = srci + dst[j]; e = e > 0.f ? e : ALPHA * e;
                float p = expf(e - m); sden += p;
                const float* wr = Wh + (size_t)j * NH;
                acc0 += p * wr[c0]; acc1 += p * wr[c1];
            }
    }
    float inv = 1.f / sden;
    float v0 = acc0 * inv, v1 = acc1 * inv;
    v0 = v0 > 0.f ? v0 : expm1f(v0);     // elu
    v1 = v1 > 0.f ? v1 : expm1f(v1);
    g_h[(size_t)i * (HEADS * NH) + h * NH + c0] = v0;
    g_h[(size_t)i * (HEADS * NH) + h * NH + c1] = v1;
}

// ---------------- layer-2 GEMM: Wh2 = h @ Wo + bo ----------------
__global__ __launch_bounds__(256) void k_gemm2(const float* __restrict__ Wo,
                                               const float* __restrict__ bo) {
    int idx = blockIdx.x * blockDim.x + threadIdx.x;
    if (idx >= NN * NC) return;
    int i = idx / NC, c = idx % NC;
    const float* hr = g_h + (size_t)i * (HEADS * NH);
    float acc = bo[c];
#pragma unroll 8
    for (int k = 0; k < HEADS * NH; k++) acc += hr[k] * Wo[k * NC + c];
    g_Wh2[idx] = acc;
}

// ---------------- layer-2 src/dst ----------------
__global__ __launch_bounds__(128) void k_srcdst2(const float* __restrict__ ao) {
    int i = blockIdx.x * 4 + (threadIdx.x >> 5);
    int lane = threadIdx.x & 31;
    const float* r = g_Wh2 + (size_t)i * NC;
    float v0 = r[lane];                               // c = 0..31
    float v1 = (lane < 8) ? r[32 + lane] : 0.f;       // c = 32..39
    float s = v0 * ao[lane]      + ((lane < 8) ? v1 * ao[32 + lane] : 0.f);
    float t = v0 * ao[NC + lane] + ((lane < 8) ? v1 * ao[NC + 32 + lane] : 0.f);
    s = warpSum(s); t = warpSum(t);
    if (lane == 0) { g_src2[i] = s; g_dst2[i] = t; }
}

// ---------------- output attention + elu + log_softmax ----------------
// block 128 = 4 warps, one row per warp.
__global__ __launch_bounds__(128) void k_att2(const float* __restrict__ abo,
                                              float* __restrict__ out) {
    __shared__ unsigned short s_nbr[4][CAP];
    __shared__ float          s_pe[4][CAP];
    int wi = threadIdx.x >> 5;
    int i  = blockIdx.x * 4 + wi;
    int lane = threadIdx.x & 31;

    const unsigned* row = g_adj + (size_t)i * ADJW;
    float srci = g_src2[i] + abo[0];

    unsigned w[4]; int myc = 0;
#pragma unroll
    for (int q = 0; q < 4; q++) { w[q] = row[lane + 32 * q]; myc += __popc(w[q]); }
    int ofs = myc;
#pragma unroll
    for (int o = 1; o < 32; o <<= 1) {
        int v = __shfl_up_sync(0xffffffffu, ofs, o);
        if (lane >= o) ofs += v;
    }
    int cnt  = __shfl_sync(0xffffffffu, ofs, 31);
    int base = ofs - myc;
#pragma unroll
    for (int q = 0; q < 4; q++) {
        unsigned ww = w[q];
        while (ww) {
            int bpos = __ffs(ww) - 1; ww &= ww - 1;
            int j = (lane + 32 * q) * 32 + bpos;
            if (base < CAP) {
                float e = srci + g_dst2[j];
                e = e > 0.f ? e : ALPHA * e;
                s_nbr[wi][base] = (unsigned short)j;
                s_pe[wi][base]  = e;
            }
            base++;
        }
    }
    __syncwarp();

    float acc0 = 0.f, acc1 = 0.f, sden;
    if (cnt > 0 && cnt <= CAP) {
        float m = -1e30f;
        for (int k = lane; k < cnt; k += 32) m = fmaxf(m, s_pe[wi][k]);
        m = warpMax(m);
        float s = 0.f;
        for (int k = lane; k < cnt; k += 32) {
            float p = expf(s_pe[wi][k] - m); s_pe[wi][k] = p; s += p;
        }
        sden = warpSum(s);
        __syncwarp();
        for (int k = 0; k < cnt; k++) {
            float p = s_pe[wi][k];
            const float* wr = g_Wh2 + (size_t)s_nbr[wi][k] * NC;
            acc0 += p * wr[lane];
            if (lane < 8) acc1 += p * wr[32 + lane];
        }
    } else if (cnt == 0) {
        for (int j = 0; j < NN; j++) {
            const float* wr = g_Wh2 + (size_t)j * NC;
            acc0 += wr[lane];
            if (lane < 8) acc1 += wr[32 + lane];
        }
        sden = (float)NN;
    } else {
        float m = -1e30f;
        for (int j = 0; j < NN; j++)
            if ((row[j >> 5] >> (j & 31)) & 1u) {
                float e = srci + g_dst2[j]; e = e > 0.f ? e : ALPHA * e;
                m = fmaxf(m, e);
            }
        sden = 0.f;
        for (int j = 0; j < NN; j++)
            if ((row[j >> 5] >> (j & 31)) & 1u) {
                float e = srci + g_dst2[j]; e = e > 0.f ? e : ALPHA * e;
                float p = expf(e - m); sden += p;
                const float* wr = g_Wh2 + (size_t)j * NC;
                acc0 += p * wr[lane];
                if (lane < 8) acc1 += p * wr[32 + lane];
            }
    }
    float inv = 1.f / sden;
    float v0 = acc0 * inv;
    float v1 = acc1 * inv;
    v0 = v0 > 0.f ? v0 : expm1f(v0);     // elu
    if (lane < 8) v1 = v1 > 0.f ? v1 : expm1f(v1);

    // log_softmax over the 40 classes within the warp
    float mx = v0;
    if (lane < 8) mx = fmaxf(mx, v1);
    mx = warpMax(mx);
    float se = expf(v0 - mx) + ((lane < 8) ? expf(v1 - mx) : 0.f);
    se = warpSum(se);
    float ls = mx + logf(se);

    out[(size_t)i * NC + lane] = v0 - ls;
    if (lane < 8) out[(size_t)i * NC + 32 + lane] = v1 - ls;
}

// ---------------- launcher ----------------
extern "C" void kernel_launch(void* const* d_in, const int* in_sizes, int n_in,
                              void* d_out, int out_size) {
    const float* x   = (const float*)d_in[0];
    const void*  ei  = d_in[1];
    const float* W1  = (const float*)d_in[2];
    const float* b1  = (const float*)d_in[3];
    const float* a1  = (const float*)d_in[4];
    const float* ab1 = (const float*)d_in[5];
    const float* Wo  = (const float*)d_in[6];
    const float* bo  = (const float*)d_in[7];
    const float* ao  = (const float*)d_in[8];
    const float* abo = (const float*)d_in[9];
    float* out = (float*)d_out;

    k_zero<<<(NN * ADJW + 255) / 256, 256>>>();
    k_detect<<<256, 256>>>(ei);
    k_scatter<<<(NE + 255) / 256, 256>>>(ei);
    k_gemm1<<<dim3(64, 4), 256>>>(x, W1, b1);
    k_srcdst1<<<NN, 128>>>(a1);
    k_att1<<<NN, 128>>>(ab1);
    k_gemm2<<<(NN * NC + 255) / 256, 256>>>(Wo, bo);
    k_srcdst2<<<NN / 4, 128>>>(ao);
    k_att2<<<NN / 4, 128>>>(abo, out);
}

// round 2
// speedup vs baseline: 1.3253x; 1.3253x over previous
#include <cuda_runtime.h>
#include <math.h>

#define NN    4096
#define NF    512
#define NH    64
#define NC    40
#define HEADS 4
#define NE    131072
#define ADJW  128          // 4096 bits / 32 per row
#define CAP   416          // neighbor list capacity per row (mean deg ~32)
#define ALPHA 0.2f

typedef unsigned long long ull;

// ---------------- scratch (device globals; no allocation allowed) ----------
__device__ __align__(16) unsigned g_adj[NN * ADJW];     // 2 MB bitmask adjacency
__device__ __align__(16) float    g_Wh1[HEADS * NN * NH];
__device__ __align__(16) float    g_src1[HEADS * NN];
__device__ __align__(16) float    g_dst1[HEADS * NN];
__device__ __align__(16) float    g_h[NN * HEADS * NH]; // [i][h*64+c] post-elu concat
__device__ __align__(16) float    g_Wh2[NN * NC];
__device__ __align__(16) float    g_src2[NN];
__device__ __align__(16) float    g_dst2[NN];

// ---------------- packed f32x2 helpers ----------------
__device__ __forceinline__ void fma2(ull& acc, ull a, ull b) {
    asm("fma.rn.f32x2 %0, %1, %2, %0;" : "+l"(acc) : "l"(a), "l"(b));
}
__device__ __forceinline__ ull splat2(float v) {
    ull r; asm("mov.b64 %0, {%1, %1};" : "=l"(r) : "f"(v)); return r;
}
__device__ __forceinline__ ull pack2(float lo, float hi) {
    ull r; asm("mov.b64 %0, {%1, %2};" : "=l"(r) : "f"(lo), "f"(hi)); return r;
}
__device__ __forceinline__ float2 unpack2(ull v) {
    float2 r; asm("mov.b64 {%0, %1}, %2;" : "=f"(r.x), "=f"(r.y) : "l"(v)); return r;
}

// ---------------- warp reductions ----------------
__device__ __forceinline__ float warpMax(float v) {
#pragma unroll
    for (int o = 16; o; o >>= 1) v = fmaxf(v, __shfl_xor_sync(0xffffffffu, v, o));
    return v;
}
__device__ __forceinline__ float warpSum(float v) {
#pragma unroll
    for (int o = 16; o; o >>= 1) v += __shfl_xor_sync(0xffffffffu, v, o);
    return v;
}

// ---------------- adjacency ----------------
__global__ void k_zero() {
    int i = blockIdx.x * blockDim.x + threadIdx.x;
    ((uint4*)g_adj)[i] = make_uint4(0u, 0u, 0u, 0u);
}

// dtype detection folded in: probe first 16 int64 words. If edge_index is
// int32-packed, the high halves are random node ids; all-zero prob (1/4096)^16.
__global__ void k_scatter(const void* e) {
    const long long* p64 = (const long long*)e;
    bool is32 = false;
#pragma unroll
    for (int q = 0; q < 16; q++) {
        long long v = p64[q];
        if (v < 0 || v >= NN) is32 = true;
    }
    int k = blockIdx.x * blockDim.x + threadIdx.x;
    if (k >= NE) return;
    int s, d;
    if (is32) {
        const int* p = (const int*)e;
        s = p[k]; d = p[k + NE];
    } else {
        s = (int)p64[k]; d = (int)p64[k + NE];
    }
    atomicOr(&g_adj[s * ADJW + (d >> 5)], 1u << (d & 31));
}

// ---------------- layer-1 GEMM: Wh1[h] = x @ W1[h] + b1[h] -----------------
// Fused over head pairs: N-tile = 128 covers heads (2*by, 2*by+1).
// grid (64, 2), 128 threads; 64x128 tile; thread = 8m x 8n via f32x2 pairs.
// Software-pipelined LDG->reg, double-buffered smem, one sync per chunk.
__global__ __launch_bounds__(128) void k_gemm1(const float* __restrict__ x,
                                               const float* __restrict__ W,
                                               const float* __restrict__ b) {
    __shared__ float As[2][16][68];
    __shared__ float Bs[2][16][128];
    int t  = threadIdx.x;
    int tx = t & 15, ty = t >> 4;
    int m0 = blockIdx.x * 64;
    int by = blockIdx.y;                      // heads 2*by, 2*by+1
    const float* W0 = W + (size_t)(2 * by) * NF * NH;
    const float* W1p = W0 + (size_t)NF * NH;

    // A: thread loads 8 consecutive k of row (t>>1)
    const float* xp = x + (size_t)(m0 + (t >> 1)) * NF + (t & 1) * 8;
    // B: q0: Bs[ty][tx*4]<-W0[k0+ty]; q1: Bs[ty+8][tx*4]<-W0[k0+ty+8];
    //    q2/q3 same rows from W1p into cols 64+tx*4
    const float* bp0 = W0  + (size_t)ty * NH + tx * 4;
    const float* bp1 = W1p + (size_t)ty * NH + tx * 4;

    float4 ra0 = *(const float4*)(xp);
    float4 ra1 = *(const float4*)(xp + 4);
    float4 rb0 = *(const float4*)(bp0);
    float4 rb1 = *(const float4*)(bp0 + 8 * NH);
    float4 rb2 = *(const float4*)(bp1);
    float4 rb3 = *(const float4*)(bp1 + 8 * NH);

    ull acc[4][8];
#pragma unroll
    for (int p = 0; p < 4; p++)
#pragma unroll
        for (int j = 0; j < 8; j++) acc[p][j] = 0ull;

    int kh = (t & 1) * 8, mA = t >> 1;

    for (int ch = 0; ch < 32; ch++) {
        int bi = ch & 1;
        As[bi][kh + 0][mA] = ra0.x; As[bi][kh + 1][mA] = ra0.y;
        As[bi][kh + 2][mA] = ra0.z; As[bi][kh + 3][mA] = ra0.w;
        As[bi][kh + 4][mA] = ra1.x; As[bi][kh + 5][mA] = ra1.y;
        As[bi][kh + 6][mA] = ra1.z; As[bi][kh + 7][mA] = ra1.w;
        *(float4*)&Bs[bi][ty    ][tx * 4]      = rb0;
        *(float4*)&Bs[bi][ty + 8][tx * 4]      = rb1;
        *(float4*)&Bs[bi][ty    ][64 + tx * 4] = rb2;
        *(float4*)&Bs[bi][ty + 8][64 + tx * 4] = rb3;
        __syncthreads();
        if (ch < 31) {
            int ko = (ch + 1) * 16;
            ra0 = *(const float4*)(xp + ko);
            ra1 = *(const float4*)(xp + ko + 4);
            rb0 = *(const float4*)(bp0 + (size_t)ko * NH);
            rb1 = *(const float4*)(bp0 + (size_t)(ko + 8) * NH);
            rb2 = *(const float4*)(bp1 + (size_t)ko * NH);
            rb3 = *(const float4*)(bp1 + (size_t)(ko + 8) * NH);
        }
#pragma unroll
        for (int kk = 0; kk < 16; kk++) {
            ull a0 = *(const ull*)&As[bi][kk][ty * 8 + 0];
            ull a1 = *(const ull*)&As[bi][kk][ty * 8 + 2];
            ull a2 = *(const ull*)&As[bi][kk][ty * 8 + 4];
            ull a3 = *(const ull*)&As[bi][kk][ty * 8 + 6];
            float4 v0 = *(const float4*)&Bs[bi][kk][tx * 4];
            float4 v1 = *(const float4*)&Bs[bi][kk][64 + tx * 4];
            ull s0 = splat2(v0.x), s1 = splat2(v0.y), s2 = splat2(v0.z), s3 = splat2(v0.w);
            ull s4 = splat2(v1.x), s5 = splat2(v1.y), s6 = splat2(v1.z), s7 = splat2(v1.w);
            fma2(acc[0][0], a0, s0); fma2(acc[0][1], a0, s1); fma2(acc[0][2], a0, s2); fma2(acc[0][3], a0, s3);
            fma2(acc[0][4], a0, s4); fma2(acc[0][5], a0, s5); fma2(acc[0][6], a0, s6); fma2(acc[0][7], a0, s7);
            fma2(acc[1][0], a1, s0); fma2(acc[1][1], a1, s1); fma2(acc[1][2], a1, s2); fma2(acc[1][3], a1, s3);
            fma2(acc[1][4], a1, s4); fma2(acc[1][5], a1, s5); fma2(acc[1][6], a1, s6); fma2(acc[1][7], a1, s7);
            fma2(acc[2][0], a2, s0); fma2(acc[2][1], a2, s1); fma2(acc[2][2], a2, s2); fma2(acc[2][3], a2, s3);
            fma2(acc[2][4], a2, s4); fma2(acc[2][5], a2, s5); fma2(acc[2][6], a2, s6); fma2(acc[2][7], a2, s7);
            fma2(acc[3][0], a3, s0); fma2(acc[3][1], a3, s1); fma2(acc[3][2], a3, s2); fma2(acc[3][3], a3, s3);
            fma2(acc[3][4], a3, s4); fma2(acc[3][5], a3, s5); fma2(acc[3][6], a3, s6); fma2(acc[3][7], a3, s7);
        }
        __syncthreads();
    }

    int hA = 2 * by, hB = 2 * by + 1;
    float4 biasA = *(const float4*)&b[hA * NH + tx * 4];
    float4 biasB = *(const float4*)&b[hB * NH + tx * 4];
#pragma unroll
    for (int p = 0; p < 4; p++) {
        int mlo = m0 + ty * 8 + 2 * p;
        float2 c0 = unpack2(acc[p][0]), c1 = unpack2(acc[p][1]);
        float2 c2 = unpack2(acc[p][2]), c3 = unpack2(acc[p][3]);
        float2 c4 = unpack2(acc[p][4]), c5 = unpack2(acc[p][5]);
        float2 c6 = unpack2(acc[p][6]), c7 = unpack2(acc[p][7]);
        *(float4*)&g_Wh1[((size_t)hA * NN + mlo)     * NH + tx * 4] =
            make_float4(c0.x + biasA.x, c1.x + biasA.y, c2.x + biasA.z, c3.x + biasA.w);
        *(float4*)&g_Wh1[((size_t)hA * NN + mlo + 1) * NH + tx * 4] =
            make_float4(c0.y + biasA.x, c1.y + biasA.y, c2.y + biasA.z, c3.y + biasA.w);
        *(float4*)&g_Wh1[((size_t)hB * NN + mlo)     * NH + tx * 4] =
            make_float4(c4.x + biasB.x, c5.x + biasB.y, c6.x + biasB.z, c7.x + biasB.w);
        *(float4*)&g_Wh1[((size_t)hB * NN + mlo + 1) * NH + tx * 4] =
            make_float4(c4.y + biasB.x, c5.y + biasB.y, c6.y + biasB.z, c7.y + biasB.w);
    }
}

// ---------------- layer-1 src/dst vectors ----------------
__global__ __launch_bounds__(128) void k_srcdst1(const float* __restrict__ a1) {
    int i = blockIdx.x;
    int h = threadIdx.x >> 5;
    int lane = threadIdx.x & 31;
    const float* whr = g_Wh1 + ((size_t)h * NN + i) * NH;
    float w0 = whr[lane], w1 = whr[lane + 32];
    const float* a = a1 + h * 2 * NH;
    float s = w0 * a[lane]      + w1 * a[lane + 32];
    float t = w0 * a[NH + lane] + w1 * a[NH + lane + 32];
    s = warpSum(s); t = warpSum(t);
    if (lane == 0) { g_src1[h * NN + i] = s; g_dst1[h * NN + i] = t; }
}

// ---------------- layer-1 sparse attention + elu + concat ----------------
__global__ __launch_bounds__(128) void k_att1(const float* __restrict__ ab1) {
    __shared__ unsigned short s_nbr[4][CAP];
    __shared__ float          s_pe[4][CAP];
    int i = blockIdx.x;
    int h = threadIdx.x >> 5, lane = threadIdx.x & 31;

    const unsigned* row = g_adj + (size_t)i * ADJW;
    const float* dst = g_dst1 + (size_t)h * NN;
    float srci = g_src1[(size_t)h * NN + i] + ab1[h];

    unsigned w[4]; int myc = 0;
#pragma unroll
    for (int q = 0; q < 4; q++) { w[q] = row[lane + 32 * q]; myc += __popc(w[q]); }
    int ofs = myc;
#pragma unroll
    for (int o = 1; o < 32; o <<= 1) {
        int v = __shfl_up_sync(0xffffffffu, ofs, o);
        if (lane >= o) ofs += v;
    }
    int cnt  = __shfl_sync(0xffffffffu, ofs, 31);
    int base = ofs - myc;
#pragma unroll
    for (int q = 0; q < 4; q++) {
        unsigned ww = w[q];
        while (ww) {
            int bpos = __ffs(ww) - 1; ww &= ww - 1;
            int j = (lane + 32 * q) * 32 + bpos;
            if (base < CAP) {
                float e = srci + dst[j];
                e = e > 0.f ? e : ALPHA * e;
                s_nbr[h][base] = (unsigned short)j;
                s_pe[h][base]  = e;
            }
            base++;
        }
    }
    __syncwarp();

    const float* Wh = g_Wh1 + (size_t)h * NN * NH;
    ull acc = 0ull; float sden;

    if (cnt > 0 && cnt <= CAP) {
        float m = -1e30f;
        for (int k = lane; k < cnt; k += 32) m = fmaxf(m, s_pe[h][k]);
        m = warpMax(m);
        float s = 0.f;
        for (int k = lane; k < cnt; k += 32) {
            float p = expf(s_pe[h][k] - m); s_pe[h][k] = p; s += p;
        }
        sden = warpSum(s);
        __syncwarp();
#pragma unroll 4
        for (int k = 0; k < cnt; k++) {
            float p = s_pe[h][k];
            int j = s_nbr[h][k];
            ull wv = *(const ull*)(Wh + (size_t)j * NH + 2 * lane);
            fma2(acc, splat2(p), wv);
        }
    } else if (cnt == 0) {
        ull one = splat2(1.f);
        for (int j = 0; j < NN; j++) {
            ull wv = *(const ull*)(Wh + (size_t)j * NH + 2 * lane);
            fma2(acc, one, wv);
        }
        sden = (float)NN;
    } else {
        float m = -1e30f;
        for (int j = 0; j < NN; j++)
            if ((row[j >> 5] >> (j & 31)) & 1u) {
                float e = srci + dst[j]; e = e > 0.f ? e : ALPHA * e;
                m = fmaxf(m, e);
            }
        sden = 0.f;
        for (int j = 0; j < NN; j++)
            if ((row[j >> 5] >> (j & 31)) & 1u) {
                float e = srci + dst[j]; e = e > 0.f ? e : ALPHA * e;
                float p = expf(e - m); sden += p;
                ull wv = *(const ull*)(Wh + (size_t)j * NH + 2 * lane);
                fma2(acc, splat2(p), wv);
            }
    }
    float inv = 1.f / sden;
    float2 v = unpack2(acc);
    v.x *= inv; v.y *= inv;
    v.x = v.x > 0.f ? v.x : expm1f(v.x);
    v.y = v.y > 0.f ? v.y : expm1f(v.y);
    *(float2*)&g_h[(size_t)i * (HEADS * NH) + h * NH + 2 * lane] = v;
}

// ---------------- layer-2 GEMM + src/dst fold -----------------------------
// grid 64, block 256. Thread: row m = bx*64 + (tid>>2), column-pair group
// g = tid&3 handles pairs [g*5, g*5+5). Wo staged in smem (40KB).
__global__ __launch_bounds__(256) void k_gemm2(const float* __restrict__ Wo,
                                               const float* __restrict__ bo,
                                               const float* __restrict__ ao) {
    __shared__ float sW[NF / 2 * NC / 2 * 0 + 256 * NC];   // 256*40 floats
    int tid = threadIdx.x;
    // stage Wo: 10240 floats = 2560 float4, 10 per thread
#pragma unroll
    for (int q = 0; q < 10; q++) {
        int f = tid + q * 256;
        *(float4*)&sW[f * 4] = *(const float4*)&Wo[f * 4];
    }
    __syncthreads();

    int m  = blockIdx.x * 64 + (tid >> 2);
    int g  = tid & 3;
    int cp0 = g * 5;
    const float* hr = g_h + (size_t)m * (HEADS * NH);

    ull acc[5];
#pragma unroll
    for (int u = 0; u < 5; u++)
        acc[u] = pack2(bo[2 * (cp0 + u)], bo[2 * (cp0 + u) + 1]);

    for (int k0 = 0; k0 < HEADS * NH; k0 += 4) {
        float4 hv = *(const float4*)(hr + k0);
#pragma unroll
        for (int q = 0; q < 4; q++) {
            float hvq = q == 0 ? hv.x : q == 1 ? hv.y : q == 2 ? hv.z : hv.w;
            ull hs = splat2(hvq);
            const float* wrow = sW + (k0 + q) * NC + 2 * cp0;
#pragma unroll
            for (int u = 0; u < 5; u++)
                fma2(acc[u], hs, *(const ull*)(wrow + 2 * u));
        }
    }

    float v[10];
    float sp = 0.f, tp = 0.f;
#pragma unroll
    for (int u = 0; u < 5; u++) {
        float2 p = unpack2(acc[u]);
        v[2 * u] = p.x; v[2 * u + 1] = p.y;
        int c = 2 * (cp0 + u);
        sp += p.x * ao[c]      + p.y * ao[c + 1];
        tp += p.x * ao[NC + c] + p.y * ao[NC + c + 1];
        *(float2*)&g_Wh2[(size_t)m * NC + c] = p;
    }
    // reduce src/dst over the 4 column groups of this row (lanes g=0..3)
    sp += __shfl_xor_sync(0xffffffffu, sp, 1);
    sp += __shfl_xor_sync(0xffffffffu, sp, 2);
    tp += __shfl_xor_sync(0xffffffffu, tp, 1);
    tp += __shfl_xor_sync(0xffffffffu, tp, 2);
    if (g == 0) { g_src2[m] = sp; g_dst2[m] = tp; }
}

// ---------------- output attention + elu + log_softmax ----------------
__global__ __launch_bounds__(128) void k_att2(const float* __restrict__ abo,
                                              float* __restrict__ out) {
    __shared__ unsigned short s_nbr[4][CAP];
    __shared__ float          s_pe[4][CAP];
    int wi = threadIdx.x >> 5;
    int i  = blockIdx.x * 4 + wi;
    int lane = threadIdx.x & 31;

    const unsigned* row = g_adj + (size_t)i * ADJW;
    float srci = g_src2[i] + abo[0];

    unsigned w[4]; int myc = 0;
#pragma unroll
    for (int q = 0; q < 4; q++) { w[q] = row[lane + 32 * q]; myc += __popc(w[q]); }
    int ofs = myc;
#pragma unroll
    for (int o = 1; o < 32; o <<= 1) {
        int v = __shfl_up_sync(0xffffffffu, ofs, o);
        if (lane >= o) ofs += v;
    }
    int cnt  = __shfl_sync(0xffffffffu, ofs, 31);
    int base = ofs - myc;
#pragma unroll
    for (int q = 0; q < 4; q++) {
        unsigned ww = w[q];
        while (ww) {
            int bpos = __ffs(ww) - 1; ww &= ww - 1;
            int j = (lane + 32 * q) * 32 + bpos;
            if (base < CAP) {
                float e = srci + g_dst2[j];
                e = e > 0.f ? e : ALPHA * e;
                s_nbr[wi][base] = (unsigned short)j;
                s_pe[wi][base]  = e;
            }
            base++;
        }
    }
    __syncwarp();

    bool act = lane < NC / 2;      // 20 active pair-lanes
    ull acc = 0ull; float sden;

    if (cnt > 0 && cnt <= CAP) {
        float m = -1e30f;
        for (int k = lane; k < cnt; k += 32) m = fmaxf(m, s_pe[wi][k]);
        m = warpMax(m);
        float s = 0.f;
        for (int k = lane; k < cnt; k += 32) {
            float p = expf(s_pe[wi][k] - m); s_pe[wi][k] = p; s += p;
        }
        sden = warpSum(s);
        __syncwarp();
#pragma unroll 4
        for (int k = 0; k < cnt; k++) {
            float p = s_pe[wi][k];
            int j = s_nbr[wi][k];
            if (act) {
                ull wv = *(const ull*)(g_Wh2 + (size_t)j * NC + 2 * lane);
                fma2(acc, splat2(p), wv);
            }
        }
    } else if (cnt == 0) {
        ull one = splat2(1.f);
        for (int j = 0; j < NN; j++)
            if (act) {
                ull wv = *(const ull*)(g_Wh2 + (size_t)j * NC + 2 * lane);
                fma2(acc, one, wv);
            }
        sden = (float)NN;
    } else {
        float m = -1e30f;
        for (int j = 0; j < NN; j++)
            if ((row[j >> 5] >> (j & 31)) & 1u) {
                float e = srci + g_dst2[j]; e = e > 0.f ? e : ALPHA * e;
                m = fmaxf(m, e);
            }
        sden = 0.f;
        for (int j = 0; j < NN; j++)
            if ((row[j >> 5] >> (j & 31)) & 1u) {
                float e = srci + g_dst2[j]; e = e > 0.f ? e : ALPHA * e;
                float p = expf(e - m); sden += p;
                if (act) {
                    ull wv = *(const ull*)(g_Wh2 + (size_t)j * NC + 2 * lane);
                    fma2(acc, splat2(p), wv);
                }
            }
    }
    float inv = 1.f / sden;
    float2 v = unpack2(acc);
    v.x *= inv; v.y *= inv;
    if (act) {
        v.x = v.x > 0.f ? v.x : expm1f(v.x);
        v.y = v.y > 0.f ? v.y : expm1f(v.y);
    }
    float mx = act ? fmaxf(v.x, v.y) : -1e30f;
    mx = warpMax(mx);
    float se = act ? (expf(v.x - mx) + expf(v.y - mx)) : 0.f;
    se = warpSum(se);
    float ls = mx + logf(se);

    if (act)
        *(float2*)&out[(size_t)i * NC + 2 * lane] = make_float2(v.x - ls, v.y - ls);
}

// ---------------- launcher ----------------
extern "C" void kernel_launch(void* const* d_in, const int* in_sizes, int n_in,
                              void* d_out, int out_size) {
    const float* x   = (const float*)d_in[0];
    const void*  ei  = d_in[1];
    const float* W1  = (const float*)d_in[2];
    const float* b1  = (const float*)d_in[3];
    const float* a1  = (const float*)d_in[4];
    const float* ab1 = (const float*)d_in[5];
    const float* Wo  = (const float*)d_in[6];
    const float* bo  = (const float*)d_in[7];
    const float* ao  = (const float*)d_in[8];
    const float* abo = (const float*)d_in[9];
    float* out = (float*)d_out;

    k_zero<<<NN * ADJW / 4 / 256, 256>>>();
    k_scatter<<<NE / 256, 256>>>(ei);
    k_gemm1<<<dim3(64, 2), 128>>>(x, W1, b1);
    k_srcdst1<<<NN, 128>>>(a1);
    k_att1<<<NN, 128>>>(ab1);
    k_gemm2<<<64, 256>>>(Wo, bo, ao);
    k_att2<<<NN / 4, 128>>>(abo, out);
}

// round 4
// speedup vs baseline: 1.3410x; 1.0118x over previous
#include <cuda_runtime.h>
#include <math.h>

#define NN    4096
#define NF    512
#define NH    64
#define NC    40
#define HEADS 4
#define NE    131072
#define ADJW  128          // 4096 bits / 32 per row
#define CAP   416          // neighbor list capacity per row (mean deg ~32)
#define ALPHA 0.2f

typedef unsigned long long ull;

// ---------------- scratch (device globals; no allocation allowed) ----------
__device__ __align__(16) unsigned g_adj[NN * ADJW];     // 2 MB bitmask adjacency
__device__ __align__(16) float    g_Wh1[HEADS * NN * NH];
__device__ __align__(16) float    g_src1[HEADS * NN];
__device__ __align__(16) float    g_dst1[HEADS * NN];
__device__ __align__(16) float    g_h[NN * HEADS * NH]; // [i][h*64+c] post-elu concat
__device__ __align__(16) float    g_Wh2[NN * NC];
__device__ __align__(16) float    g_src2[NN];
__device__ __align__(16) float    g_dst2[NN];

// ---------------- packed f32x2 helpers ----------------
__device__ __forceinline__ void fma2(ull& acc, ull a, ull b) {
    asm("fma.rn.f32x2 %0, %1, %2, %0;" : "+l"(acc) : "l"(a), "l"(b));
}
__device__ __forceinline__ ull add2(ull a, ull b) {
    ull r; asm("add.rn.f32x2 %0, %1, %2;" : "=l"(r) : "l"(a), "l"(b)); return r;
}
__device__ __forceinline__ ull splat2(float v) {
    ull r; asm("mov.b64 %0, {%1, %1};" : "=l"(r) : "f"(v)); return r;
}
__device__ __forceinline__ ull pack2(float lo, float hi) {
    ull r; asm("mov.b64 %0, {%1, %2};" : "=l"(r) : "f"(lo), "f"(hi)); return r;
}
__device__ __forceinline__ float2 unpack2(ull v) {
    float2 r; asm("mov.b64 {%0, %1}, %2;" : "=f"(r.x), "=f"(r.y) : "l"(v)); return r;
}

// ---------------- warp reductions ----------------
__device__ __forceinline__ float warpMax(float v) {
#pragma unroll
    for (int o = 16; o; o >>= 1) v = fmaxf(v, __shfl_xor_sync(0xffffffffu, v, o));
    return v;
}
__device__ __forceinline__ float warpSum(float v) {
#pragma unroll
    for (int o = 16; o; o >>= 1) v += __shfl_xor_sync(0xffffffffu, v, o);
    return v;
}
// reduce packed f32x2 across a 16-lane half
__device__ __forceinline__ ull halfSum2(ull v) {
#pragma unroll
    for (int o = 1; o <= 8; o <<= 1)
        v = add2(v, __shfl_xor_sync(0xffffffffu, v, o));
    return v;
}

// ---------------- adjacency ----------------
__global__ void k_zero() {
    int i = blockIdx.x * blockDim.x + threadIdx.x;
    ((uint4*)g_adj)[i] = make_uint4(0u, 0u, 0u, 0u);
}

__global__ void k_scatter(const void* e) {
    const long long* p64 = (const long long*)e;
    bool is32 = false;
#pragma unroll
    for (int q = 0; q < 16; q++) {
        long long v = p64[q];
        if (v < 0 || v >= NN) is32 = true;
    }
    int k = blockIdx.x * blockDim.x + threadIdx.x;
    if (k >= NE) return;
    int s, d;
    if (is32) {
        const int* p = (const int*)e;
        s = p[k]; d = p[k + NE];
    } else {
        s = (int)p64[k]; d = (int)p64[k + NE];
    }
    atomicOr(&g_adj[s * ADJW + (d >> 5)], 1u << (d & 31));
}

// ---------------- layer-1 GEMM + fused src/dst epilogue --------------------
// grid (64, 2), 128 threads; 64x128 tile (2 heads); thread = 8m x 8n f32x2.
__global__ __launch_bounds__(128) void k_gemm1(const float* __restrict__ x,
                                               const float* __restrict__ W,
                                               const float* __restrict__ b,
                                               const float* __restrict__ a1) {
    __shared__ float As[2][16][68];
    __shared__ float Bs[2][16][128];
    int t  = threadIdx.x;
    int tx = t & 15, ty = t >> 4;
    int m0 = blockIdx.x * 64;
    int by = blockIdx.y;                      // heads 2*by, 2*by+1
    const float* W0  = W + (size_t)(2 * by) * NF * NH;
    const float* W1p = W0 + (size_t)NF * NH;

    const float* xp  = x + (size_t)(m0 + (t >> 1)) * NF + (t & 1) * 8;
    const float* bp0 = W0  + (size_t)ty * NH + tx * 4;
    const float* bp1 = W1p + (size_t)ty * NH + tx * 4;

    float4 ra0 = *(const float4*)(xp);
    float4 ra1 = *(const float4*)(xp + 4);
    float4 rb0 = *(const float4*)(bp0);
    float4 rb1 = *(const float4*)(bp0 + 8 * NH);
    float4 rb2 = *(const float4*)(bp1);
    float4 rb3 = *(const float4*)(bp1 + 8 * NH);

    ull acc[4][8];
#pragma unroll
    for (int p = 0; p < 4; p++)
#pragma unroll
        for (int j = 0; j < 8; j++) acc[p][j] = 0ull;

    int kh = (t & 1) * 8, mA = t >> 1;

    for (int ch = 0; ch < 32; ch++) {
        int bi = ch & 1;
        As[bi][kh + 0][mA] = ra0.x; As[bi][kh + 1][mA] = ra0.y;
        As[bi][kh + 2][mA] = ra0.z; As[bi][kh + 3][mA] = ra0.w;
        As[bi][kh + 4][mA] = ra1.x; As[bi][kh + 5][mA] = ra1.y;
        As[bi][kh + 6][mA] = ra1.z; As[bi][kh + 7][mA] = ra1.w;
        *(float4*)&Bs[bi][ty    ][tx * 4]      = rb0;
        *(float4*)&Bs[bi][ty + 8][tx * 4]      = rb1;
        *(float4*)&Bs[bi][ty    ][64 + tx * 4] = rb2;
        *(float4*)&Bs[bi][ty + 8][64 + tx * 4] = rb3;
        __syncthreads();
        if (ch < 31) {
            int ko = (ch + 1) * 16;
            ra0 = *(const float4*)(xp + ko);
            ra1 = *(const float4*)(xp + ko + 4);
            rb0 = *(const float4*)(bp0 + (size_t)ko * NH);
            rb1 = *(const float4*)(bp0 + (size_t)(ko + 8) * NH);
            rb2 = *(const float4*)(bp1 + (size_t)ko * NH);
            rb3 = *(const float4*)(bp1 + (size_t)(ko + 8) * NH);
        }
#pragma unroll
        for (int kk = 0; kk < 16; kk++) {
            ull a0 = *(const ull*)&As[bi][kk][ty * 8 + 0];
            ull a1r = *(const ull*)&As[bi][kk][ty * 8 + 2];
            ull a2 = *(const ull*)&As[bi][kk][ty * 8 + 4];
            ull a3 = *(const ull*)&As[bi][kk][ty * 8 + 6];
            float4 v0 = *(const float4*)&Bs[bi][kk][tx * 4];
            float4 v1 = *(const float4*)&Bs[bi][kk][64 + tx * 4];
            ull s0 = splat2(v0.x), s1 = splat2(v0.y), s2 = splat2(v0.z), s3 = splat2(v0.w);
            ull s4 = splat2(v1.x), s5 = splat2(v1.y), s6 = splat2(v1.z), s7 = splat2(v1.w);
            fma2(acc[0][0], a0, s0); fma2(acc[0][1], a0, s1); fma2(acc[0][2], a0, s2); fma2(acc[0][3], a0, s3);
            fma2(acc[0][4], a0, s4); fma2(acc[0][5], a0, s5); fma2(acc[0][6], a0, s6); fma2(acc[0][7], a0, s7);
            fma2(acc[1][0], a1r, s0); fma2(acc[1][1], a1r, s1); fma2(acc[1][2], a1r, s2); fma2(acc[1][3], a1r, s3);
            fma2(acc[1][4], a1r, s4); fma2(acc[1][5], a1r, s5); fma2(acc[1][6], a1r, s6); fma2(acc[1][7], a1r, s7);
            fma2(acc[2][0], a2, s0); fma2(acc[2][1], a2, s1); fma2(acc[2][2], a2, s2); fma2(acc[2][3], a2, s3);
            fma2(acc[2][4], a2, s4); fma2(acc[2][5], a2, s5); fma2(acc[2][6], a2, s6); fma2(acc[2][7], a2, s7);
            fma2(acc[3][0], a3, s0); fma2(acc[3][1], a3, s1); fma2(acc[3][2], a3, s2); fma2(acc[3][3], a3, s3);
            fma2(acc[3][4], a3, s4); fma2(acc[3][5], a3, s5); fma2(acc[3][6], a3, s6); fma2(acc[3][7], a3, s7);
        }
        __syncthreads();
    }

    int hA = 2 * by, hB = 2 * by + 1;
    float4 biasA = *(const float4*)&b[hA * NH + tx * 4];
    float4 biasB = *(const float4*)&b[hB * NH + tx * 4];

    // a-vector (src,dst) pairs for this thread's 4 columns, per head
    const float* aA = a1 + hA * 2 * NH;
    const float* aB = a1 + hB * 2 * NH;
    ull apA[4], apB[4];
#pragma unroll
    for (int q = 0; q < 4; q++) {
        apA[q] = pack2(aA[tx * 4 + q], aA[NH + tx * 4 + q]);
        apB[q] = pack2(aB[tx * 4 + q], aB[NH + tx * 4 + q]);
    }

#pragma unroll
    for (int p = 0; p < 4; p++) {
        int mlo = m0 + ty * 8 + 2 * p;
        float2 c0 = unpack2(acc[p][0]), c1 = unpack2(acc[p][1]);
        float2 c2 = unpack2(acc[p][2]), c3 = unpack2(acc[p][3]);
        float2 c4 = unpack2(acc[p][4]), c5 = unpack2(acc[p][5]);
        float2 c6 = unpack2(acc[p][6]), c7 = unpack2(acc[p][7]);
        float4 vA0 = make_float4(c0.x + biasA.x, c1.x + biasA.y, c2.x + biasA.z, c3.x + biasA.w);
        float4 vA1 = make_float4(c0.y + biasA.x, c1.y + biasA.y, c2.y + biasA.z, c3.y + biasA.w);
        float4 vB0 = make_float4(c4.x + biasB.x, c5.x + biasB.y, c6.x + biasB.z, c7.x + biasB.w);
        float4 vB1 = make_float4(c4.y + biasB.x, c5.y + biasB.y, c6.y + biasB.z, c7.y + biasB.w);
        *(float4*)&g_Wh1[((size_t)hA * NN + mlo)     * NH + tx * 4] = vA0;
        *(float4*)&g_Wh1[((size_t)hA * NN + mlo + 1) * NH + tx * 4] = vA1;
        *(float4*)&g_Wh1[((size_t)hB * NN + mlo)     * NH + tx * 4] = vB0;
        *(float4*)&g_Wh1[((size_t)hB * NN + mlo + 1) * NH + tx * 4] = vB1;

        // fused src/dst partial dots + 16-lane butterfly
        ull sdA0 = 0ull, sdA1 = 0ull, sdB0 = 0ull, sdB1 = 0ull;
        fma2(sdA0, splat2(vA0.x), apA[0]); fma2(sdA0, splat2(vA0.y), apA[1]);
        fma2(sdA0, splat2(vA0.z), apA[2]); fma2(sdA0, splat2(vA0.w), apA[3]);
        fma2(sdA1, splat2(vA1.x), apA[0]); fma2(sdA1, splat2(vA1.y), apA[1]);
        fma2(sdA1, splat2(vA1.z), apA[2]); fma2(sdA1, splat2(vA1.w), apA[3]);
        fma2(sdB0, splat2(vB0.x), apB[0]); fma2(sdB0, splat2(vB0.y), apB[1]);
        fma2(sdB0, splat2(vB0.z), apB[2]); fma2(sdB0, splat2(vB0.w), apB[3]);
        fma2(sdB1, splat2(vB1.x), apB[0]); fma2(sdB1, splat2(vB1.y), apB[1]);
        fma2(sdB1, splat2(vB1.z), apB[2]); fma2(sdB1, splat2(vB1.w), apB[3]);
        sdA0 = halfSum2(sdA0); sdA1 = halfSum2(sdA1);
        sdB0 = halfSum2(sdB0); sdB1 = halfSum2(sdB1);
        if (tx == 0) {
            float2 r;
            r = unpack2(sdA0); g_src1[hA * NN + mlo]     = r.x; g_dst1[hA * NN + mlo]     = r.y;
            r = unpack2(sdA1); g_src1[hA * NN + mlo + 1] = r.x; g_dst1[hA * NN + mlo + 1] = r.y;
            r = unpack2(sdB0); g_src1[hB * NN + mlo]     = r.x; g_dst1[hB * NN + mlo]     = r.y;
            r = unpack2(sdB1); g_src1[hB * NN + mlo + 1] = r.x; g_dst1[hB * NN + mlo + 1] = r.y;
        }
    }
}

// ---------------- layer-1 sparse attention + elu + concat ----------------
// block 128 = 4 warps, one (row, head) per warp; split-warp float4 aggregation.
__global__ __launch_bounds__(128) void k_att1(const float* __restrict__ ab1) {
    __shared__ unsigned short s_nbr[4][CAP];
    __shared__ float          s_pe[4][CAP];
    int i = blockIdx.x;
    int h = threadIdx.x >> 5, lane = threadIdx.x & 31;
    int half = lane >> 4, sl = lane & 15;

    const unsigned* row = g_adj + (size_t)i * ADJW;
    const float* dst = g_dst1 + (size_t)h * NN;
    float srci = g_src1[(size_t)h * NN + i] + ab1[h];

    // Phase A: deterministic neighbor gather (popc + warp exclusive scan).
    unsigned w[4]; int myc = 0;
#pragma unroll
    for (int q = 0; q < 4; q++) { w[q] = row[lane + 32 * q]; myc += __popc(w[q]); }
    int ofs = myc;
#pragma unroll
    for (int o = 1; o < 32; o <<= 1) {
        int v = __shfl_up_sync(0xffffffffu, ofs, o);
        if (lane >= o) ofs += v;
    }
    int cnt  = __shfl_sync(0xffffffffu, ofs, 31);
    int base = ofs - myc;
#pragma unroll
    for (int q = 0; q < 4; q++) {
        unsigned ww = w[q];
        while (ww) {
            int bpos = __ffs(ww) - 1; ww &= ww - 1;
            int j = (lane + 32 * q) * 32 + bpos;
            if (base < CAP) {
                float e = srci + dst[j];
                e = e > 0.f ? e : ALPHA * e;
                s_nbr[h][base] = (unsigned short)j;
                s_pe[h][base]  = e;
            }
            base++;
        }
    }
    __syncwarp();

    const float* Wh = g_Wh1 + (size_t)h * NN * NH;
    ull accA = 0ull, accB = 0ull; float sden;

    if (cnt > 0 && cnt <= CAP) {
        float m = -1e30f;
        for (int k = lane; k < cnt; k += 32) m = fmaxf(m, s_pe[h][k]);
        m = warpMax(m);
        float s = 0.f;
        for (int k = lane; k < cnt; k += 32) {
            float p = expf(s_pe[h][k] - m); s_pe[h][k] = p; s += p;
        }
        sden = warpSum(s);
        __syncwarp();
#pragma unroll 4
        for (int k = half; k < cnt; k += 2) {
            float p = s_pe[h][k];
            int j = s_nbr[h][k];
            float4 wv = *(const float4*)(Wh + (size_t)j * NH + sl * 4);
            ull ps = splat2(p);
            fma2(accA, ps, pack2(wv.x, wv.y));
            fma2(accB, ps, pack2(wv.z, wv.w));
        }
    } else if (cnt == 0) {
        ull one = splat2(1.f);
#pragma unroll 4
        for (int j = half; j < NN; j += 2) {
            float4 wv = *(const float4*)(Wh + (size_t)j * NH + sl * 4);
            fma2(accA, one, pack2(wv.x, wv.y));
            fma2(accB, one, pack2(wv.z, wv.w));
        }
        sden = (float)NN;
    } else {
        // overflow fallback: exact serial path (never expected)
        float m = -1e30f;
        for (int j = 0; j < NN; j++)
            if ((row[j >> 5] >> (j & 31)) & 1u) {
                float e = srci + dst[j]; e = e > 0.f ? e : ALPHA * e;
                m = fmaxf(m, e);
            }
        sden = 0.f;
        for (int j = 0; j < NN; j++)
            if ((row[j >> 5] >> (j & 31)) & 1u) {
                float e = srci + dst[j]; e = e > 0.f ? e : ALPHA * e;
                float p = expf(e - m); sden += p;
                float4 wv = *(const float4*)(Wh + (size_t)j * NH + sl * 4);
                if (half == 0) {
                    ull ps = splat2(p);
                    fma2(accA, ps, pack2(wv.x, wv.y));
                    fma2(accB, ps, pack2(wv.z, wv.w));
                }
            }
    }
    // combine halves
    accA = add2(accA, __shfl_xor_sync(0xffffffffu, accA, 16));
    accB = add2(accB, __shfl_xor_sync(0xffffffffu, accB, 16));
    if (half == 0) {
        float inv = 1.f / sden;
        float2 a = unpack2(accA), bb = unpack2(accB);
        float4 v = make_float4(a.x * inv, a.y * inv, bb.x * inv, bb.y * inv);
        v.x = v.x > 0.f ? v.x : expm1f(v.x);
        v.y = v.y > 0.f ? v.y : expm1f(v.y);
        v.z = v.z > 0.f ? v.z : expm1f(v.z);
        v.w = v.w > 0.f ? v.w : expm1f(v.w);
        *(float4*)&g_h[(size_t)i * (HEADS * NH) + h * NH + sl * 4] = v;
    }
}

// ---------------- layer-2 GEMM + src/dst fold -----------------------------
__global__ __launch_bounds__(256) void k_gemm2(const float* __restrict__ Wo,
                                               const float* __restrict__ bo,
                                               const float* __restrict__ ao) {
    __shared__ float sW[256 * NC];
    int tid = threadIdx.x;
#pragma unroll
    for (int q = 0; q < 10; q++) {
        int f = tid + q * 256;
        *(float4*)&sW[f * 4] = *(const float4*)&Wo[f * 4];
    }
    __syncthreads();

    int m  = blockIdx.x * 64 + (tid >> 2);
    int g  = tid & 3;
    int cp0 = g * 5;
    const float* hr = g_h + (size_t)m * (HEADS * NH);

    ull acc[5];
#pragma unroll
    for (int u = 0; u < 5; u++)
        acc[u] = pack2(bo[2 * (cp0 + u)], bo[2 * (cp0 + u) + 1]);

    for (int k0 = 0; k0 < HEADS * NH; k0 += 4) {
        float4 hv = *(const float4*)(hr + k0);
#pragma unroll
        for (int q = 0; q < 4; q++) {
            float hvq = q == 0 ? hv.x : q == 1 ? hv.y : q == 2 ? hv.z : hv.w;
            ull hs = splat2(hvq);
            const float* wrow = sW + (k0 + q) * NC + 2 * cp0;
#pragma unroll
            for (int u = 0; u < 5; u++)
                fma2(acc[u], hs, *(const ull*)(wrow + 2 * u));
        }
    }

    float sp = 0.f, tp = 0.f;
#pragma unroll
    for (int u = 0; u < 5; u++) {
        float2 p = unpack2(acc[u]);
        int c = 2 * (cp0 + u);
        sp += p.x * ao[c]      + p.y * ao[c + 1];
        tp += p.x * ao[NC + c] + p.y * ao[NC + c + 1];
        *(float2*)&g_Wh2[(size_t)m * NC + c] = p;
    }
    sp += __shfl_xor_sync(0xffffffffu, sp, 1);
    sp += __shfl_xor_sync(0xffffffffu, sp, 2);
    tp += __shfl_xor_sync(0xffffffffu, tp, 1);
    tp += __shfl_xor_sync(0xffffffffu, tp, 2);
    if (g == 0) { g_src2[m] = sp; g_dst2[m] = tp; }
}

// ---------------- output attention + elu + log_softmax ----------------
__global__ __launch_bounds__(128) void k_att2(const float* __restrict__ abo,
                                              float* __restrict__ out) {
    __shared__ unsigned short s_nbr[4][CAP];
    __shared__ float          s_pe[4][CAP];
    int wi = threadIdx.x >> 5;
    int i  = blockIdx.x * 4 + wi;
    int lane = threadIdx.x & 31;

    const unsigned* row = g_adj + (size_t)i * ADJW;
    float srci = g_src2[i] + abo[0];

    unsigned w[4]; int myc = 0;
#pragma unroll
    for (int q = 0; q < 4; q++) { w[q] = row[lane + 32 * q]; myc += __popc(w[q]); }
    int ofs = myc;
#pragma unroll
    for (int o = 1; o < 32; o <<= 1) {
        int v = __shfl_up_sync(0xffffffffu, ofs, o);
        if (lane >= o) ofs += v;
    }
    int cnt  = __shfl_sync(0xffffffffu, ofs, 31);
    int base = ofs - myc;
#pragma unroll
    for (int q = 0; q < 4; q++) {
        unsigned ww = w[q];
        while (ww) {
            int bpos = __ffs(ww) - 1; ww &= ww - 1;
            int j = (lane + 32 * q) * 32 + bpos;
            if (base < CAP) {
                float e = srci + g_dst2[j];
                e = e > 0.f ? e : ALPHA * e;
                s_nbr[wi][base] = (unsigned short)j;
                s_pe[wi][base]  = e;
            }
            base++;
        }
    }
    __syncwarp();

    bool act = lane < NC / 2;      // 20 active pair-lanes
    ull acc = 0ull; float sden;

    if (cnt > 0 && cnt <= CAP) {
        float m = -1e30f;
        for (int k = lane; k < cnt; k += 32) m = fmaxf(m, s_pe[wi][k]);
        m = warpMax(m);
        float s = 0.f;
        for (int k = lane; k < cnt; k += 32) {
            float p = expf(s_pe[wi][k] - m); s_pe[wi][k] = p; s += p;
        }
        sden = warpSum(s);
        __syncwarp();
#pragma unroll 4
        for (int k = 0; k < cnt; k++) {
            float p = s_pe[wi][k];
            int j = s_nbr[wi][k];
            if (act) {
                ull wv = *(const ull*)(g_Wh2 + (size_t)j * NC + 2 * lane);
                fma2(acc, splat2(p), wv);
            }
        }
    } else if (cnt == 0) {
        ull one = splat2(1.f);
        for (int j = 0; j < NN; j++)
            if (act) {
                ull wv = *(const ull*)(g_Wh2 + (size_t)j * NC + 2 * lane);
                fma2(acc, one, wv);
            }
        sden = (float)NN;
    } else {
        float m = -1e30f;
        for (int j = 0; j < NN; j++)
            if ((row[j >> 5] >> (j & 31)) & 1u) {
                float e = srci + g_dst2[j]; e = e > 0.f ? e : ALPHA * e;
                m = fmaxf(m, e);
            }
        sden = 0.f;
        for (int j = 0; j < NN; j++)
            if ((row[j >> 5] >> (j & 31)) & 1u) {
                float e = srci + g_dst2[j]; e = e > 0.f ? e : ALPHA * e;
                float p = expf(e - m); sden += p;
                if (act) {
                    ull wv = *(const ull*)(g_Wh2 + (size_t)j * NC + 2 * lane);
                    fma2(acc, splat2(p), wv);
                }
            }
    }
    float inv = 1.f / sden;
    float2 v = unpack2(acc);
    v.x *= inv; v.y *= inv;
    if (act) {
        v.x = v.x > 0.f ? v.x : expm1f(v.x);
        v.y = v.y > 0.f ? v.y : expm1f(v.y);
    }
    float mx = act ? fmaxf(v.x, v.y) : -1e30f;
    mx = warpMax(mx);
    float se = act ? (expf(v.x - mx) + expf(v.y - mx)) : 0.f;
    se = warpSum(se);
    float ls = mx + logf(se);

    if (act)
        *(float2*)&out[(size_t)i * NC + 2 * lane] = make_float2(v.x - ls, v.y - ls);
}

// ---------------- launcher ----------------
extern "C" void kernel_launch(void* const* d_in, const int* in_sizes, int n_in,
                              void* d_out, int out_size) {
    const float* x   = (const float*)d_in[0];
    const void*  ei  = d_in[1];
    const float* W1  = (const float*)d_in[2];
    const float* b1  = (const float*)d_in[3];
    const float* a1  = (const float*)d_in[4];
    const float* ab1 = (const float*)d_in[5];
    const float* Wo  = (const float*)d_in[6];
    const float* bo  = (const float*)d_in[7];
    const float* ao  = (const float*)d_in[8];
    const float* abo = (const float*)d_in[9];
    float* out = (float*)d_out;

    k_zero<<<NN * ADJW / 4 / 256, 256>>>();
    k_scatter<<<NE / 256, 256>>>(ei);
    k_gemm1<<<dim3(64, 2), 128>>>(x, W1, b1, a1);
    k_att1<<<NN, 128>>>(ab1);
    k_gemm2<<<64, 256>>>(Wo, bo, ao);
    k_att2<<<NN / 4, 128>>>(abo, out);
}

// round 5
// speedup vs baseline: 1.4103x; 1.0517x over previous
#include <cuda_runtime.h>
#include <math.h>

#define NN    4096
#define NF    512
#define NH    64
#define NC    40
#define HEADS 4
#define NE    131072
#define ADJW  128          // 4096 bits / 32 per row
#define CAP   416          // neighbor list capacity per row (mean deg ~32)
#define ALPHA 0.2f

typedef unsigned long long ull;

// ---------------- scratch (device globals; no allocation allowed) ----------
__device__ __align__(16) unsigned g_adj[NN * ADJW];     // 2 MB bitmask adjacency
__device__ __align__(16) float    g_Wh1[HEADS * NN * NH];
__device__ __align__(16) float    g_srcT1[NN * HEADS];  // [i][h] transposed
__device__ __align__(16) float    g_dstT1[NN * HEADS];  // [i][h] transposed
__device__ __align__(16) float    g_h[NN * HEADS * NH]; // [i][h*64+c] post-elu concat
__device__ __align__(16) float    g_Wh2[NN * NC];
__device__ __align__(16) float    g_src2[NN];
__device__ __align__(16) float    g_dst2[NN];

// ---------------- packed f32x2 helpers ----------------
__device__ __forceinline__ void fma2(ull& acc, ull a, ull b) {
    asm("fma.rn.f32x2 %0, %1, %2, %0;" : "+l"(acc) : "l"(a), "l"(b));
}
__device__ __forceinline__ ull add2(ull a, ull b) {
    ull r; asm("add.rn.f32x2 %0, %1, %2;" : "=l"(r) : "l"(a), "l"(b)); return r;
}
__device__ __forceinline__ ull splat2(float v) {
    ull r; asm("mov.b64 %0, {%1, %1};" : "=l"(r) : "f"(v)); return r;
}
__device__ __forceinline__ ull pack2(float lo, float hi) {
    ull r; asm("mov.b64 %0, {%1, %2};" : "=l"(r) : "f"(lo), "f"(hi)); return r;
}
__device__ __forceinline__ float2 unpack2(ull v) {
    float2 r; asm("mov.b64 {%0, %1}, %2;" : "=f"(r.x), "=f"(r.y) : "l"(v)); return r;
}

// ---------------- warp reductions ----------------
__device__ __forceinline__ float warpMax(float v) {
#pragma unroll
    for (int o = 16; o; o >>= 1) v = fmaxf(v, __shfl_xor_sync(0xffffffffu, v, o));
    return v;
}
__device__ __forceinline__ float warpSum(float v) {
#pragma unroll
    for (int o = 16; o; o >>= 1) v += __shfl_xor_sync(0xffffffffu, v, o);
    return v;
}
__device__ __forceinline__ ull halfSum2(ull v) {
#pragma unroll
    for (int o = 1; o <= 8; o <<= 1)
        v = add2(v, __shfl_xor_sync(0xffffffffu, v, o));
    return v;
}

// ---------------- adjacency ----------------
__global__ void k_zero() {
    int i = blockIdx.x * blockDim.x + threadIdx.x;
    ((uint4*)g_adj)[i] = make_uint4(0u, 0u, 0u, 0u);
}

__global__ void k_scatter(const void* e) {
    const long long* p64 = (const long long*)e;
    bool is32 = false;
#pragma unroll
    for (int q = 0; q < 16; q++) {
        long long v = p64[q];
        if (v < 0 || v >= NN) is32 = true;
    }
    int k = blockIdx.x * blockDim.x + threadIdx.x;
    if (k >= NE) return;
    int s, d;
    if (is32) {
        const int* p = (const int*)e;
        s = p[k]; d = p[k + NE];
    } else {
        s = (int)p64[k]; d = (int)p64[k + NE];
    }
    atomicOr(&g_adj[s * ADJW + (d >> 5)], 1u << (d & 31));
}

// ---------------- layer-1 GEMM + fused src/dst epilogue --------------------
// grid (64, 2), 128 threads; 64x128 tile (2 heads); thread = 8m x 8n f32x2.
__global__ __launch_bounds__(128) void k_gemm1(const float* __restrict__ x,
                                               const float* __restrict__ W,
                                               const float* __restrict__ b,
                                               const float* __restrict__ a1) {
    __shared__ float As[2][16][68];
    __shared__ float Bs[2][16][128];
    int t  = threadIdx.x;
    int tx = t & 15, ty = t >> 4;
    int m0 = blockIdx.x * 64;
    int by = blockIdx.y;                      // heads 2*by, 2*by+1
    const float* W0  = W + (size_t)(2 * by) * NF * NH;
    const float* W1p = W0 + (size_t)NF * NH;

    const float* xp  = x + (size_t)(m0 + (t >> 1)) * NF + (t & 1) * 8;
    const float* bp0 = W0  + (size_t)ty * NH + tx * 4;
    const float* bp1 = W1p + (size_t)ty * NH + tx * 4;

    float4 ra0 = *(const float4*)(xp);
    float4 ra1 = *(const float4*)(xp + 4);
    float4 rb0 = *(const float4*)(bp0);
    float4 rb1 = *(const float4*)(bp0 + 8 * NH);
    float4 rb2 = *(const float4*)(bp1);
    float4 rb3 = *(const float4*)(bp1 + 8 * NH);

    ull acc[4][8];
#pragma unroll
    for (int p = 0; p < 4; p++)
#pragma unroll
        for (int j = 0; j < 8; j++) acc[p][j] = 0ull;

    int kh = (t & 1) * 8, mA = t >> 1;

    for (int ch = 0; ch < 32; ch++) {
        int bi = ch & 1;
        As[bi][kh + 0][mA] = ra0.x; As[bi][kh + 1][mA] = ra0.y;
        As[bi][kh + 2][mA] = ra0.z; As[bi][kh + 3][mA] = ra0.w;
        As[bi][kh + 4][mA] = ra1.x; As[bi][kh + 5][mA] = ra1.y;
        As[bi][kh + 6][mA] = ra1.z; As[bi][kh + 7][mA] = ra1.w;
        *(float4*)&Bs[bi][ty    ][tx * 4]      = rb0;
        *(float4*)&Bs[bi][ty + 8][tx * 4]      = rb1;
        *(float4*)&Bs[bi][ty    ][64 + tx * 4] = rb2;
        *(float4*)&Bs[bi][ty + 8][64 + tx * 4] = rb3;
        __syncthreads();
        if (ch < 31) {
            int ko = (ch + 1) * 16;
            ra0 = *(const float4*)(xp + ko);
            ra1 = *(const float4*)(xp + ko + 4);
            rb0 = *(const float4*)(bp0 + (size_t)ko * NH);
            rb1 = *(const float4*)(bp0 + (size_t)(ko + 8) * NH);
            rb2 = *(const float4*)(bp1 + (size_t)ko * NH);
            rb3 = *(const float4*)(bp1 + (size_t)(ko + 8) * NH);
        }
#pragma unroll
        for (int kk = 0; kk < 16; kk++) {
            ull a0 = *(const ull*)&As[bi][kk][ty * 8 + 0];
            ull a1r = *(const ull*)&As[bi][kk][ty * 8 + 2];
            ull a2 = *(const ull*)&As[bi][kk][ty * 8 + 4];
            ull a3 = *(const ull*)&As[bi][kk][ty * 8 + 6];
            float4 v0 = *(const float4*)&Bs[bi][kk][tx * 4];
            float4 v1 = *(const float4*)&Bs[bi][kk][64 + tx * 4];
            ull s0 = splat2(v0.x), s1 = splat2(v0.y), s2 = splat2(v0.z), s3 = splat2(v0.w);
            ull s4 = splat2(v1.x), s5 = splat2(v1.y), s6 = splat2(v1.z), s7 = splat2(v1.w);
            fma2(acc[0][0], a0, s0); fma2(acc[0][1], a0, s1); fma2(acc[0][2], a0, s2); fma2(acc[0][3], a0, s3);
            fma2(acc[0][4], a0, s4); fma2(acc[0][5], a0, s5); fma2(acc[0][6], a0, s6); fma2(acc[0][7], a0, s7);
            fma2(acc[1][0], a1r, s0); fma2(acc[1][1], a1r, s1); fma2(acc[1][2], a1r, s2); fma2(acc[1][3], a1r, s3);
            fma2(acc[1][4], a1r, s4); fma2(acc[1][5], a1r, s5); fma2(acc[1][6], a1r, s6); fma2(acc[1][7], a1r, s7);
            fma2(acc[2][0], a2, s0); fma2(acc[2][1], a2, s1); fma2(acc[2][2], a2, s2); fma2(acc[2][3], a2, s3);
            fma2(acc[2][4], a2, s4); fma2(acc[2][5], a2, s5); fma2(acc[2][6], a2, s6); fma2(acc[2][7], a2, s7);
            fma2(acc[3][0], a3, s0); fma2(acc[3][1], a3, s1); fma2(acc[3][2], a3, s2); fma2(acc[3][3], a3, s3);
            fma2(acc[3][4], a3, s4); fma2(acc[3][5], a3, s5); fma2(acc[3][6], a3, s6); fma2(acc[3][7], a3, s7);
        }
        __syncthreads();
    }

    int hA = 2 * by, hB = 2 * by + 1;
    float4 biasA = *(const float4*)&b[hA * NH + tx * 4];
    float4 biasB = *(const float4*)&b[hB * NH + tx * 4];

    const float* aA = a1 + hA * 2 * NH;
    const float* aB = a1 + hB * 2 * NH;
    ull apA[4], apB[4];
#pragma unroll
    for (int q = 0; q < 4; q++) {
        apA[q] = pack2(aA[tx * 4 + q], aA[NH + tx * 4 + q]);
        apB[q] = pack2(aB[tx * 4 + q], aB[NH + tx * 4 + q]);
    }

#pragma unroll
    for (int p = 0; p < 4; p++) {
        int mlo = m0 + ty * 8 + 2 * p;
        float2 c0 = unpack2(acc[p][0]), c1 = unpack2(acc[p][1]);
        float2 c2 = unpack2(acc[p][2]), c3 = unpack2(acc[p][3]);
        float2 c4 = unpack2(acc[p][4]), c5 = unpack2(acc[p][5]);
        float2 c6 = unpack2(acc[p][6]), c7 = unpack2(acc[p][7]);
        float4 vA0 = make_float4(c0.x + biasA.x, c1.x + biasA.y, c2.x + biasA.z, c3.x + biasA.w);
        float4 vA1 = make_float4(c0.y + biasA.x, c1.y + biasA.y, c2.y + biasA.z, c3.y + biasA.w);
        float4 vB0 = make_float4(c4.x + biasB.x, c5.x + biasB.y, c6.x + biasB.z, c7.x + biasB.w);
        float4 vB1 = make_float4(c4.y + biasB.x, c5.y + biasB.y, c6.y + biasB.z, c7.y + biasB.w);
        *(float4*)&g_Wh1[((size_t)hA * NN + mlo)     * NH + tx * 4] = vA0;
        *(float4*)&g_Wh1[((size_t)hA * NN + mlo + 1) * NH + tx * 4] = vA1;
        *(float4*)&g_Wh1[((size_t)hB * NN + mlo)     * NH + tx * 4] = vB0;
        *(float4*)&g_Wh1[((size_t)hB * NN + mlo + 1) * NH + tx * 4] = vB1;

        // fused src/dst partial dots + 16-lane butterfly
        ull sdA0 = 0ull, sdA1 = 0ull, sdB0 = 0ull, sdB1 = 0ull;
        fma2(sdA0, splat2(vA0.x), apA[0]); fma2(sdA0, splat2(vA0.y), apA[1]);
        fma2(sdA0, splat2(vA0.z), apA[2]); fma2(sdA0, splat2(vA0.w), apA[3]);
        fma2(sdA1, splat2(vA1.x), apA[0]); fma2(sdA1, splat2(vA1.y), apA[1]);
        fma2(sdA1, splat2(vA1.z), apA[2]); fma2(sdA1, splat2(vA1.w), apA[3]);
        fma2(sdB0, splat2(vB0.x), apB[0]); fma2(sdB0, splat2(vB0.y), apB[1]);
        fma2(sdB0, splat2(vB0.z), apB[2]); fma2(sdB0, splat2(vB0.w), apB[3]);
        fma2(sdB1, splat2(vB1.x), apB[0]); fma2(sdB1, splat2(vB1.y), apB[1]);
        fma2(sdB1, splat2(vB1.z), apB[2]); fma2(sdB1, splat2(vB1.w), apB[3]);
        sdA0 = halfSum2(sdA0); sdA1 = halfSum2(sdA1);
        sdB0 = halfSum2(sdB0); sdB1 = halfSum2(sdB1);
        if (tx == 0) {
            float2 r;
            r = unpack2(sdA0); g_srcT1[mlo * 4 + hA]       = r.x; g_dstT1[mlo * 4 + hA]       = r.y;
            r = unpack2(sdA1); g_srcT1[(mlo + 1) * 4 + hA] = r.x; g_dstT1[(mlo + 1) * 4 + hA] = r.y;
            r = unpack2(sdB0); g_srcT1[mlo * 4 + hB]       = r.x; g_dstT1[mlo * 4 + hB]       = r.y;
            r = unpack2(sdB1); g_srcT1[(mlo + 1) * 4 + hB] = r.x; g_dstT1[(mlo + 1) * 4 + hB] = r.y;
        }
    }
}

// ---------------- layer-1 sparse attention + elu + concat ----------------
// block 128 threads = one row. Block-wide gather ONCE; then warp h does
// softmax + aggregation for head h.
__global__ __launch_bounds__(128) void k_att1(const float* __restrict__ ab1) {
    __shared__ unsigned short s_nbr[CAP];
    __shared__ float          s_p[4][CAP];
    __shared__ int            s_wtot[4];
    int i = blockIdx.x;
    int t = threadIdx.x;
    int h = t >> 5, lane = t & 31;
    int half = lane >> 4, sl = lane & 15;

    const unsigned* row = g_adj + (size_t)i * ADJW;

    // --- block-wide gather: thread t owns adjacency word t ---
    unsigned w = row[t];
    int c = __popc(w);
    int ofs = c;
#pragma unroll
    for (int o = 1; o < 32; o <<= 1) {
        int v = __shfl_up_sync(0xffffffffu, ofs, o);
        if (lane >= o) ofs += v;
    }
    if (lane == 31) s_wtot[h] = ofs;        // inclusive warp total
    __syncthreads();
    int wbase = 0;
#pragma unroll
    for (int q = 0; q < 4; q++) wbase += (q < h) ? s_wtot[q] : 0;
    int cnt = s_wtot[0] + s_wtot[1] + s_wtot[2] + s_wtot[3];
    int base = wbase + ofs - c;
    while (w) {
        int b = __ffs(w) - 1; w &= w - 1;
        if (base < CAP) s_nbr[base] = (unsigned short)(t * 32 + b);
        base++;
    }
    __syncthreads();

    // --- per-head softmax + aggregation (warp h) ---
    float srci = g_srcT1[i * 4 + h] + ab1[h];
    const float* Wh = g_Wh1 + (size_t)h * NN * NH;
    ull accA = 0ull, accB = 0ull; float sden;

    if (cnt > 0 && cnt <= CAP) {
        float m = -1e30f;
        for (int k = lane; k < cnt; k += 32) {
            int j = s_nbr[k];
            float e = srci + g_dstT1[j * 4 + h];
            e = e > 0.f ? e : ALPHA * e;
            s_p[h][k] = e;
            m = fmaxf(m, e);
        }
        m = warpMax(m);
        float s = 0.f;
        for (int k = lane; k < cnt; k += 32) {
            float p = __expf(s_p[h][k] - m); s_p[h][k] = p; s += p;
        }
        sden = warpSum(s);
        __syncwarp();
#pragma unroll 4
        for (int k = half; k < cnt; k += 2) {
            float p = s_p[h][k];
            int j = s_nbr[k];
            float4 wv = *(const float4*)(Wh + (size_t)j * NH + sl * 4);
            ull ps = splat2(p);
            fma2(accA, ps, pack2(wv.x, wv.y));
            fma2(accB, ps, pack2(wv.z, wv.w));
        }
    } else if (cnt == 0) {
        ull one = splat2(1.f);
#pragma unroll 4
        for (int j = half; j < NN; j += 2) {
            float4 wv = *(const float4*)(Wh + (size_t)j * NH + sl * 4);
            fma2(accA, one, pack2(wv.x, wv.y));
            fma2(accB, one, pack2(wv.z, wv.w));
        }
        sden = (float)NN;
    } else {
        // overflow fallback: exact serial path (never expected)
        float m = -1e30f;
        for (int j = 0; j < NN; j++)
            if ((row[j >> 5] >> (j & 31)) & 1u) {
                float e = srci + g_dstT1[j * 4 + h]; e = e > 0.f ? e : ALPHA * e;
                m = fmaxf(m, e);
            }
        sden = 0.f;
        for (int j = 0; j < NN; j++)
            if ((row[j >> 5] >> (j & 31)) & 1u) {
                float e = srci + g_dstT1[j * 4 + h]; e = e > 0.f ? e : ALPHA * e;
                float p = __expf(e - m); sden += p;
                float4 wv = *(const float4*)(Wh + (size_t)j * NH + sl * 4);
                if (half == 0) {
                    ull ps = splat2(p);
                    fma2(accA, ps, pack2(wv.x, wv.y));
                    fma2(accB, ps, pack2(wv.z, wv.w));
                }
            }
    }
    accA = add2(accA, __shfl_xor_sync(0xffffffffu, accA, 16));
    accB = add2(accB, __shfl_xor_sync(0xffffffffu, accB, 16));
    if (half == 0) {
        float inv = 1.f / sden;
        float2 a = unpack2(accA), bb = unpack2(accB);
        float4 v = make_float4(a.x * inv, a.y * inv, bb.x * inv, bb.y * inv);
        v.x = v.x > 0.f ? v.x : expm1f(v.x);
        v.y = v.y > 0.f ? v.y : expm1f(v.y);
        v.z = v.z > 0.f ? v.z : expm1f(v.z);
        v.w = v.w > 0.f ? v.w : expm1f(v.w);
        *(float4*)&g_h[(size_t)i * (HEADS * NH) + h * NH + sl * 4] = v;
    }
}

// ---------------- layer-2 GEMM + src/dst fold -----------------------------
__global__ __launch_bounds__(256) void k_gemm2(const float* __restrict__ Wo,
                                               const float* __restrict__ bo,
                                               const float* __restrict__ ao) {
    __shared__ float sW[256 * NC];
    int tid = threadIdx.x;
#pragma unroll
    for (int q = 0; q < 10; q++) {
        int f = tid + q * 256;
        *(float4*)&sW[f * 4] = *(const float4*)&Wo[f * 4];
    }
    __syncthreads();

    int m  = blockIdx.x * 64 + (tid >> 2);
    int g  = tid & 3;
    int cp0 = g * 5;
    const float* hr = g_h + (size_t)m * (HEADS * NH);

    ull acc[5];
#pragma unroll
    for (int u = 0; u < 5; u++)
        acc[u] = pack2(bo[2 * (cp0 + u)], bo[2 * (cp0 + u) + 1]);

    for (int k0 = 0; k0 < HEADS * NH; k0 += 4) {
        float4 hv = *(const float4*)(hr + k0);
#pragma unroll
        for (int q = 0; q < 4; q++) {
            float hvq = q == 0 ? hv.x : q == 1 ? hv.y : q == 2 ? hv.z : hv.w;
            ull hs = splat2(hvq);
            const float* wrow = sW + (k0 + q) * NC + 2 * cp0;
#pragma unroll
            for (int u = 0; u < 5; u++)
                fma2(acc[u], hs, *(const ull*)(wrow + 2 * u));
        }
    }

    float sp = 0.f, tp = 0.f;
#pragma unroll
    for (int u = 0; u < 5; u++) {
        float2 p = unpack2(acc[u]);
        int c = 2 * (cp0 + u);
        sp += p.x * ao[c]      + p.y * ao[c + 1];
        tp += p.x * ao[NC + c] + p.y * ao[NC + c + 1];
        *(float2*)&g_Wh2[(size_t)m * NC + c] = p;
    }
    sp += __shfl_xor_sync(0xffffffffu, sp, 1);
    sp += __shfl_xor_sync(0xffffffffu, sp, 2);
    tp += __shfl_xor_sync(0xffffffffu, tp, 1);
    tp += __shfl_xor_sync(0xffffffffu, tp, 2);
    if (g == 0) { g_src2[m] = sp; g_dst2[m] = tp; }
}

// ---------------- output attention + elu + log_softmax ----------------
__global__ __launch_bounds__(128) void k_att2(const float* __restrict__ abo,
                                              float* __restrict__ out) {
    __shared__ unsigned short s_nbr[4][CAP];
    __shared__ float          s_pe[4][CAP];
    int wi = threadIdx.x >> 5;
    int i  = blockIdx.x * 4 + wi;
    int lane = threadIdx.x & 31;

    const unsigned* row = g_adj + (size_t)i * ADJW;
    float srci = g_src2[i] + abo[0];

    unsigned w[4]; int myc = 0;
#pragma unroll
    for (int q = 0; q < 4; q++) { w[q] = row[lane + 32 * q]; myc += __popc(w[q]); }
    int ofs = myc;
#pragma unroll
    for (int o = 1; o < 32; o <<= 1) {
        int v = __shfl_up_sync(0xffffffffu, ofs, o);
        if (lane >= o) ofs += v;
    }
    int cnt  = __shfl_sync(0xffffffffu, ofs, 31);
    int base = ofs - myc;
#pragma unroll
    for (int q = 0; q < 4; q++) {
        unsigned ww = w[q];
        while (ww) {
            int bpos = __ffs(ww) - 1; ww &= ww - 1;
            int j = (lane + 32 * q) * 32 + bpos;
            if (base < CAP) {
                float e = srci + g_dst2[j];
                e = e > 0.f ? e : ALPHA * e;
                s_nbr[wi][base] = (unsigned short)j;
                s_pe[wi][base]  = e;
            }
            base++;
        }
    }
    __syncwarp();

    bool act = lane < NC / 2;      // 20 active pair-lanes
    ull acc = 0ull; float sden;

    if (cnt > 0 && cnt <= CAP) {
        float m = -1e30f;
        for (int k = lane; k < cnt; k += 32) m = fmaxf(m, s_pe[wi][k]);
        m = warpMax(m);
        float s = 0.f;
        for (int k = lane; k < cnt; k += 32) {
            float p = __expf(s_pe[wi][k] - m); s_pe[wi][k] = p; s += p;
        }
        sden = warpSum(s);
        __syncwarp();
#pragma unroll 4
        for (int k = 0; k < cnt; k++) {
            float p = s_pe[wi][k];
            int j = s_nbr[wi][k];
            if (act) {
                ull wv = *(const ull*)(g_Wh2 + (size_t)j * NC + 2 * lane);
                fma2(acc, splat2(p), wv);
            }
        }
    } else if (cnt == 0) {
        ull one = splat2(1.f);
        for (int j = 0; j < NN; j++)
            if (act) {
                ull wv = *(const ull*)(g_Wh2 + (size_t)j * NC + 2 * lane);
                fma2(acc, one, wv);
            }
        sden = (float)NN;
    } else {
        float m = -1e30f;
        for (int j = 0; j < NN; j++)
            if ((row[j >> 5] >> (j & 31)) & 1u) {
                float e = srci + g_dst2[j]; e = e > 0.f ? e : ALPHA * e;
                m = fmaxf(m, e);
            }
        sden = 0.f;
        for (int j = 0; j < NN; j++)
            if ((row[j >> 5] >> (j & 31)) & 1u) {
                float e = srci + g_dst2[j]; e = e > 0.f ? e : ALPHA * e;
                float p = __expf(e - m); sden += p;
                if (act) {
                    ull wv = *(const ull*)(g_Wh2 + (size_t)j * NC + 2 * lane);
                    fma2(acc, splat2(p), wv);
                }
            }
    }
    float inv = 1.f / sden;
    float2 v = unpack2(acc);
    v.x *= inv; v.y *= inv;
    if (act) {
        v.x = v.x > 0.f ? v.x : expm1f(v.x);
        v.y = v.y > 0.f ? v.y : expm1f(v.y);
    }
    float mx = act ? fmaxf(v.x, v.y) : -1e30f;
    mx = warpMax(mx);
    float se = act ? (__expf(v.x - mx) + __expf(v.y - mx)) : 0.f;
    se = warpSum(se);
    float ls = mx + __logf(se);

    if (act)
        *(float2*)&out[(size_t)i * NC + 2 * lane] = make_float2(v.x - ls, v.y - ls);
}

// ---------------- launcher ----------------
extern "C" void kernel_launch(void* const* d_in, const int* in_sizes, int n_in,
                              void* d_out, int out_size) {
    const float* x   = (const float*)d_in[0];
    const void*  ei  = d_in[1];
    const float* W1  = (const float*)d_in[2];
    const float* b1  = (const float*)d_in[3];
    const float* a1  = (const float*)d_in[4];
    const float* ab1 = (const float*)d_in[5];
    const float* Wo  = (const float*)d_in[6];
    const float* bo  = (const float*)d_in[7];
    const float* ao  = (const float*)d_in[8];
    const float* abo = (const float*)d_in[9];
    float* out = (float*)d_out;

    k_zero<<<NN * ADJW / 4 / 256, 256>>>();
    k_scatter<<<NE / 256, 256>>>(ei);
    k_gemm1<<<dim3(64, 2), 128>>>(x, W1, b1, a1);
    k_att1<<<NN, 128>>>(ab1);
    k_gemm2<<<64, 256>>>(Wo, bo, ao);
    k_att2<<<NN / 4, 128>>>(abo, out);
}